// round 1
// baseline (speedup 1.0000x reference)
#include <cuda_runtime.h>
#include <cuda_bf16.h>
#include <cstdint>

#define NTOK 16384
#define DMODEL 2048
#define NGRP 8
#define HDG 256
#define DH 512   // k * hdg

// ---------------- scratch (no allocs allowed) ----------------
__device__ __align__(16) __nv_bfloat16 g_hin[(size_t)NTOK * DH];   // 16 MB gathered, gated inputs
__device__ __align__(16) __nv_bfloat16 g_wm[(size_t)DH * DH];      // 512 KB bf16 weights
__device__ int g_idx[NTOK * 2];                                    // top-2 group indices per token

// ---------------- kernel 0: Wm fp32 -> bf16 ----------------
__global__ void convert_wm(const float* __restrict__ Wm) {
    int i = blockIdx.x * 256 + threadIdx.x;   // grid 1024*256 == 262144 exactly
    g_wm[i] = __float2bfloat16(Wm[i]);
}

// ---------------- kernel 1: gate + passthrough copy + gather ----------------
__global__ __launch_bounds__(256) void gate_kernel(const float* __restrict__ x,
                                                   const float* __restrict__ Wg,
                                                   float* __restrict__ out) {
    __shared__ float xs[DMODEL];
    __shared__ float wsum[8][8];
    __shared__ float sG[2];
    __shared__ int   sI[2];

    const int tok  = blockIdx.x;
    const int tid  = threadIdx.x;
    const int lane = tid & 31;
    const int warp = tid >> 5;

    const float4* xr   = (const float4*)(x + (size_t)tok * DMODEL);
    float4*       orow = (float4*)(out + (size_t)tok * DMODEL);

    // load row into smem + passthrough copy to out
    float4 v0 = xr[tid];
    float4 v1 = xr[tid + 256];
    ((float4*)xs)[tid]       = v0;
    ((float4*)xs)[tid + 256] = v1;
    orow[tid]       = v0;
    orow[tid + 256] = v1;
    __syncthreads();

    // logits: each thread accumulates partials for all 8 groups
    float acc[NGRP];
#pragma unroll
    for (int j = 0; j < NGRP; j++) acc[j] = 0.f;
#pragma unroll
    for (int t = 0; t < DMODEL / 256; t++) {
        int i = tid + t * 256;
        float xv = xs[i];
        const float* wr = Wg + i * NGRP;
#pragma unroll
        for (int j = 0; j < NGRP; j++) acc[j] += xv * wr[j];
    }
    // warp reduce
#pragma unroll
    for (int j = 0; j < NGRP; j++) {
#pragma unroll
        for (int o = 16; o > 0; o >>= 1)
            acc[j] += __shfl_xor_sync(0xffffffffu, acc[j], o);
    }
    if (lane == 0) {
#pragma unroll
        for (int j = 0; j < NGRP; j++) wsum[warp][j] = acc[j];
    }
    __syncthreads();

    if (tid == 0) {
        float l[NGRP];
#pragma unroll
        for (int j = 0; j < NGRP; j++) {
            float s = 0.f;
#pragma unroll
            for (int w = 0; w < 8; w++) s += wsum[w][j];
            l[j] = s;
        }
        float m = l[0];
#pragma unroll
        for (int j = 1; j < NGRP; j++) m = fmaxf(m, l[j]);
        float e[NGRP], s = 0.f;
#pragma unroll
        for (int j = 0; j < NGRP; j++) { e[j] = expf(l[j] - m); s += e[j]; }
        // top-2 (strict > keeps lowest index on tie, matching lax.top_k)
        int i0 = 0;
#pragma unroll
        for (int j = 1; j < NGRP; j++) if (e[j] > e[i0]) i0 = j;
        int i1 = (i0 == 0) ? 1 : 0;
#pragma unroll
        for (int j = 0; j < NGRP; j++) if (j != i0 && e[j] > e[i1]) i1 = j;
        float inv = 1.f / s;
        sG[0] = e[i0] * inv;  sG[1] = e[i1] * inv;
        sI[0] = i0;           sI[1] = i1;
        g_idx[tok * 2 + 0] = i0;
        g_idx[tok * 2 + 1] = i1;
    }
    __syncthreads();

    // gather + gate -> g_hin (bf16), 256 threads each write one bf16x2
    if (tid < 256) {
        int p    = tid;           // pair index, covers elements 2p, 2p+1
        int half = p >> 7;        // 0: slot0 (cols 0..255), 1: slot1
        float gate = sG[half];
        int base = sI[half] * HDG + ((p * 2) & (HDG - 1));
        __nv_bfloat162 hv = __floats2bfloat162_rn(gate * xs[base], gate * xs[base + 1]);
        ((__nv_bfloat162*)g_hin)[(size_t)tok * (DH / 2) + p] = hv;
    }
}

// ---------------- kernel 2: GEMM [16384,512]x[512,512] bf16 -> fp32, scatter epilogue ----------------
// BM=64, BN=64, BK=32, 128 threads (4 warps, 2x2)
__global__ __launch_bounds__(128) void gemm_scatter(const float* __restrict__ bias,
                                                    float* __restrict__ out) {
    __shared__ __nv_bfloat16 As[64][40];   // +8 pad, row = 80B (16B-aligned stride)
    __shared__ __nv_bfloat16 Bs[32][72];   // +8 pad, row = 144B

    const int tid  = threadIdx.x;
    const int lane = tid & 31;
    const int warp = tid >> 5;
    const int wm   = warp >> 1;   // warp row (0..1) -> 32 M-rows
    const int wn   = warp & 1;    // warp col (0..1) -> 32 N-cols
    const int bmk  = blockIdx.x;  // M tile: rows bmk*64
    const int bn   = blockIdx.y;  // N tile: cols bn*64

    float acc[2][4][4];
#pragma unroll
    for (int a = 0; a < 2; a++)
#pragma unroll
        for (int b = 0; b < 4; b++)
#pragma unroll
            for (int c = 0; c < 4; c++) acc[a][b][c] = 0.f;

    for (int kt = 0; kt < DH; kt += 32) {
        // load A tile: 64 rows x 32 cols bf16 (4 uint4 per row)
#pragma unroll
        for (int t = 0; t < 2; t++) {
            int q = tid + t * 128;
            int r = q >> 2, c = (q & 3) * 8;
            *(uint4*)&As[r][c] =
                *(const uint4*)(g_hin + (size_t)(bmk * 64 + r) * DH + kt + c);
        }
        // load B tile: 32 rows x 64 cols bf16 (8 uint4 per row)
#pragma unroll
        for (int t = 0; t < 2; t++) {
            int q = tid + t * 128;
            int r = q >> 3, c = (q & 7) * 8;
            *(uint4*)&Bs[r][c] =
                *(const uint4*)(g_wm + (size_t)(kt + r) * DH + bn * 64 + c);
        }
        __syncthreads();

#pragma unroll
        for (int ks = 0; ks < 2; ks++) {
            // A fragments via ldmatrix x4
            uint32_t a[2][4];
#pragma unroll
            for (int mt = 0; mt < 2; mt++) {
                int row = wm * 32 + mt * 16 + (lane & 15);
                int col = ks * 16 + (lane >> 4) * 8;
                uint32_t addr = (uint32_t)__cvta_generic_to_shared(&As[row][col]);
                asm volatile(
                    "ldmatrix.sync.aligned.m8n8.x4.shared.b16 {%0,%1,%2,%3}, [%4];"
                    : "=r"(a[mt][0]), "=r"(a[mt][1]), "=r"(a[mt][2]), "=r"(a[mt][3])
                    : "r"(addr));
            }
            // B fragments via ldmatrix x4 trans (two 8-col tiles per ldmatrix)
            uint32_t b[4][2];
#pragma unroll
            for (int half = 0; half < 2; half++) {
                int row = ks * 16 + (lane & 15);
                int col = wn * 32 + half * 16 + (lane >> 4) * 8;
                uint32_t addr = (uint32_t)__cvta_generic_to_shared(&Bs[row][col]);
                uint32_t r0, r1, r2, r3;
                asm volatile(
                    "ldmatrix.sync.aligned.m8n8.x4.trans.shared.b16 {%0,%1,%2,%3}, [%4];"
                    : "=r"(r0), "=r"(r1), "=r"(r2), "=r"(r3)
                    : "r"(addr));
                b[half * 2 + 0][0] = r0; b[half * 2 + 0][1] = r1;
                b[half * 2 + 1][0] = r2; b[half * 2 + 1][1] = r3;
            }
#pragma unroll
            for (int mt = 0; mt < 2; mt++)
#pragma unroll
                for (int nt = 0; nt < 4; nt++) {
                    asm volatile(
                        "mma.sync.aligned.m16n8k16.row.col.f32.bf16.bf16.f32 "
                        "{%0,%1,%2,%3}, {%4,%5,%6,%7}, {%8,%9}, {%0,%1,%2,%3};"
                        : "+f"(acc[mt][nt][0]), "+f"(acc[mt][nt][1]),
                          "+f"(acc[mt][nt][2]), "+f"(acc[mt][nt][3])
                        : "r"(a[mt][0]), "r"(a[mt][1]), "r"(a[mt][2]), "r"(a[mt][3]),
                          "r"(b[nt][0]), "r"(b[nt][1]));
                }
        }
        __syncthreads();
    }

    // epilogue: add bias, scatter into out at selected group.
    // This block's 64 columns lie entirely in one selection slot:
    const int gsel = bn >> 2;  // (bn*64)/256
#pragma unroll
    for (int mt = 0; mt < 2; mt++) {
#pragma unroll
        for (int rr = 0; rr < 2; rr++) {
            int tok = bmk * 64 + wm * 32 + mt * 16 + (lane >> 2) + rr * 8;
            int grp = g_idx[tok * 2 + gsel];
            float* orow = out + (size_t)tok * DMODEL + grp * HDG;
#pragma unroll
            for (int nt = 0; nt < 4; nt++) {
                int c  = bn * 64 + wn * 32 + nt * 8 + (lane & 3) * 2;
                int cl = c & (HDG - 1);
                float2 bv = *(const float2*)(bias + c);
                float2 v;
                v.x = acc[mt][nt][rr * 2 + 0] + bv.x;
                v.y = acc[mt][nt][rr * 2 + 1] + bv.y;
                *(float2*)(orow + cl) = v;
            }
        }
    }
}

// ---------------- launch ----------------
extern "C" void kernel_launch(void* const* d_in, const int* in_sizes, int n_in,
                              void* d_out, int out_size) {
    const float* x    = (const float*)d_in[0];
    const float* Wg   = (const float*)d_in[1];
    const float* Wm   = (const float*)d_in[2];
    const float* bias = (const float*)d_in[3];
    float* out = (float*)d_out;

    convert_wm<<<1024, 256>>>(Wm);
    gate_kernel<<<NTOK, 256>>>(x, Wg, out);
    dim3 grid(NTOK / 64, DH / 64);
    gemm_scatter<<<grid, 128>>>(bias, out);
}

// round 2
// speedup vs baseline: 2.4061x; 2.4061x over previous
#include <cuda_runtime.h>
#include <cuda_bf16.h>
#include <cstdint>

#define NTOK 16384
#define DMODEL 2048
#define NGRP 8
#define HDG 256
#define DH 512   // k * hdg
#define TOKPB 8  // tokens per gate block

// ---------------- scratch (no allocs allowed) ----------------
__device__ __align__(16) __nv_bfloat16 g_hin[(size_t)NTOK * DH];   // 16 MB gathered, gated inputs
__device__ __align__(16) __nv_bfloat16 g_wm[(size_t)DH * DH];      // 512 KB bf16 weights
__device__ int g_idx[NTOK * 2];                                    // top-2 group indices per token

// ---------------- kernel 0: Wm fp32 -> bf16 ----------------
__global__ void convert_wm(const float* __restrict__ Wm) {
    int i = blockIdx.x * 256 + threadIdx.x;   // 1024*256 == 262144 exactly
    g_wm[i] = __float2bfloat16(Wm[i]);
}

// ---------------- kernel 1: gate + passthrough copy + gather ----------------
// 8 tokens per block, 256 threads. Wg cached in registers (each thread owns
// 8 rows of Wg corresponding to its 8 x-elements), reused across 8 tokens.
__global__ __launch_bounds__(256) void gate_kernel(const float* __restrict__ x,
                                                   const float* __restrict__ Wg,
                                                   float* __restrict__ out) {
    __shared__ __nv_bfloat16 xs[TOKPB][DMODEL];      // 32 KB
    __shared__ float wsum[TOKPB][8][NGRP];           // 2 KB
    __shared__ float sG[TOKPB][2];
    __shared__ int   sI[TOKPB][2];

    const int tid  = threadIdx.x;
    const int lane = tid & 31;
    const int warp = tid >> 5;
    const size_t tok0 = (size_t)blockIdx.x * TOKPB;

    // Register-cache Wg rows for this thread's 8 elements:
    //   elements 4*tid .. 4*tid+3 and 1024+4*tid .. 1024+4*tid+3
    // Each row of Wg is 8 floats = 2 float4 (coalesced: thread covers 128B contiguous).
    float4 wg[16];
    const float4* Wg4 = (const float4*)Wg;
#pragma unroll
    for (int c = 0; c < 4; c++) {
        int e = 4 * tid + c;
        wg[2 * c]     = Wg4[e * 2];
        wg[2 * c + 1] = Wg4[e * 2 + 1];
    }
#pragma unroll
    for (int c = 0; c < 4; c++) {
        int e = 1024 + 4 * tid + c;
        wg[8 + 2 * c]     = Wg4[e * 2];
        wg[8 + 2 * c + 1] = Wg4[e * 2 + 1];
    }

    // Phase 1: per token -- stream row (copy to out), stage bf16 in smem, logits.
#pragma unroll 1
    for (int t = 0; t < TOKPB; t++) {
        const float4* xr   = (const float4*)(x + (tok0 + t) * DMODEL);
        float4*       orow = (float4*)(out + (tok0 + t) * DMODEL);
        float4 v0 = xr[tid];
        float4 v1 = xr[tid + 256];
        orow[tid]       = v0;
        orow[tid + 256] = v1;
        __nv_bfloat162* xsr = (__nv_bfloat162*)xs[t];
        xsr[2 * tid]           = __floats2bfloat162_rn(v0.x, v0.y);
        xsr[2 * tid + 1]       = __floats2bfloat162_rn(v0.z, v0.w);
        xsr[512 + 2 * tid]     = __floats2bfloat162_rn(v1.x, v1.y);
        xsr[512 + 2 * tid + 1] = __floats2bfloat162_rn(v1.z, v1.w);

        float acc[NGRP];
#pragma unroll
        for (int j = 0; j < NGRP; j++) acc[j] = 0.f;
        const float* p0 = &v0.x;
        const float* p1 = &v1.x;
#pragma unroll
        for (int c = 0; c < 4; c++) {
            float xv = p0[c];
            acc[0] += xv * wg[2 * c].x;  acc[1] += xv * wg[2 * c].y;
            acc[2] += xv * wg[2 * c].z;  acc[3] += xv * wg[2 * c].w;
            acc[4] += xv * wg[2 * c + 1].x;  acc[5] += xv * wg[2 * c + 1].y;
            acc[6] += xv * wg[2 * c + 1].z;  acc[7] += xv * wg[2 * c + 1].w;
        }
#pragma unroll
        for (int c = 0; c < 4; c++) {
            float xv = p1[c];
            acc[0] += xv * wg[8 + 2 * c].x;  acc[1] += xv * wg[8 + 2 * c].y;
            acc[2] += xv * wg[8 + 2 * c].z;  acc[3] += xv * wg[8 + 2 * c].w;
            acc[4] += xv * wg[8 + 2 * c + 1].x;  acc[5] += xv * wg[8 + 2 * c + 1].y;
            acc[6] += xv * wg[8 + 2 * c + 1].z;  acc[7] += xv * wg[8 + 2 * c + 1].w;
        }
#pragma unroll
        for (int j = 0; j < NGRP; j++) {
#pragma unroll
            for (int o = 16; o > 0; o >>= 1)
                acc[j] += __shfl_xor_sync(0xffffffffu, acc[j], o);
        }
        if (lane == 0) {
#pragma unroll
            for (int j = 0; j < NGRP; j++) wsum[t][warp][j] = acc[j];
        }
    }
    __syncthreads();

    // Phase 2: lanes 0..7 of warp 0 each do one token's softmax + top-2.
    if (tid < TOKPB) {
        int t = tid;
        float l[NGRP];
#pragma unroll
        for (int j = 0; j < NGRP; j++) {
            float s = 0.f;
#pragma unroll
            for (int w = 0; w < 8; w++) s += wsum[t][w][j];
            l[j] = s;
        }
        float m = l[0];
#pragma unroll
        for (int j = 1; j < NGRP; j++) m = fmaxf(m, l[j]);
        float e[NGRP], s = 0.f;
#pragma unroll
        for (int j = 0; j < NGRP; j++) { e[j] = expf(l[j] - m); s += e[j]; }
        int i0 = 0;
#pragma unroll
        for (int j = 1; j < NGRP; j++) if (e[j] > e[i0]) i0 = j;
        int i1 = (i0 == 0) ? 1 : 0;
#pragma unroll
        for (int j = 0; j < NGRP; j++) if (j != i0 && e[j] > e[i1]) i1 = j;
        float inv = 1.f / s;
        sG[t][0] = e[i0] * inv;  sG[t][1] = e[i1] * inv;
        sI[t][0] = i0;           sI[t][1] = i1;
        g_idx[(tok0 + t) * 2 + 0] = i0;
        g_idx[(tok0 + t) * 2 + 1] = i1;
    }
    __syncthreads();

    // Phase 3: gather + gate -> g_hin (bf16x2 per thread per token).
#pragma unroll
    for (int t = 0; t < TOKPB; t++) {
        int p    = tid;                  // pair index 0..255
        int half = p >> 7;
        float gate = sG[t][half];
        int base = sI[t][half] * HDG + ((p * 2) & (HDG - 1));
        float a = __bfloat162float(xs[t][base]);
        float b = __bfloat162float(xs[t][base + 1]);
        ((__nv_bfloat162*)g_hin)[(tok0 + t) * (DH / 2) + p] =
            __floats2bfloat162_rn(gate * a, gate * b);
    }
}

// ---------------- kernel 2: GEMM [16384,512]x[512,512] bf16 -> fp32, scatter epilogue --------
// BM=128, BN=64, BK=64, 256 threads (8 warps, 4x2). cp.async double buffered,
// XOR-swizzled smem (conflict-free ldmatrix, zero padding, exactly 48KB).
#define BM 128
#define BN 64
#define BK 64

__device__ __forceinline__ uint32_t sw_off(uint32_t row, uint32_t g) {
    // byte offset in a [rows][64 bf16] tile: row stride 128B, 16B-granule XOR swizzle
    return row * 128u + ((g ^ (row & 7u)) * 16u);
}

__global__ __launch_bounds__(256) void gemm_scatter(const float* __restrict__ bias,
                                                    float* __restrict__ out) {
    __shared__ __nv_bfloat16 As[2][BM * BK];   // 2 * 16 KB
    __shared__ __nv_bfloat16 Bs[2][BK * BN];   // 2 * 8 KB   -> 48 KB total

    const int tid  = threadIdx.x;
    const int lane = tid & 31;
    const int warp = tid >> 5;
    const int wm   = warp >> 1;   // 0..3 -> 32 M-rows each
    const int wn   = warp & 1;    // 0..1 -> 32 N-cols each
    const int bn   = blockIdx.x;  // 0..7
    const int bm   = blockIdx.y;  // 0..127

    const __nv_bfloat16* Ag = g_hin + (size_t)(bm * BM) * DH;
    const __nv_bfloat16* Bg = g_wm + (size_t)(bn * BN);

    const uint32_t sA0 = (uint32_t)__cvta_generic_to_shared(&As[0][0]);
    const uint32_t sA1 = (uint32_t)__cvta_generic_to_shared(&As[1][0]);
    const uint32_t sB0 = (uint32_t)__cvta_generic_to_shared(&Bs[0][0]);
    const uint32_t sB1 = (uint32_t)__cvta_generic_to_shared(&Bs[1][0]);

    auto load_stage = [&](int s, int kt) {
        uint32_t sA = s ? sA1 : sA0;
        uint32_t sB = s ? sB1 : sB0;
#pragma unroll
        for (int i = 0; i < 4; i++) {         // A: 128x64 bf16 = 1024 16B chunks
            int q = tid + i * 256;
            int r = q >> 3, g = q & 7;
            const __nv_bfloat16* src = Ag + (size_t)r * DH + kt + g * 8;
            asm volatile("cp.async.cg.shared.global [%0], [%1], 16;\n"
                         :: "r"(sA + sw_off(r, g)), "l"(src));
        }
#pragma unroll
        for (int i = 0; i < 2; i++) {         // B: 64x64 bf16 = 512 16B chunks
            int q = tid + i * 256;
            int r = q >> 3, g = q & 7;
            const __nv_bfloat16* src = Bg + (size_t)(kt + r) * DH + g * 8;
            asm volatile("cp.async.cg.shared.global [%0], [%1], 16;\n"
                         :: "r"(sB + sw_off(r, g)), "l"(src));
        }
        asm volatile("cp.async.commit_group;\n");
    };

    float acc[2][4][4];
#pragma unroll
    for (int a = 0; a < 2; a++)
#pragma unroll
        for (int b = 0; b < 4; b++)
#pragma unroll
            for (int c = 0; c < 4; c++) acc[a][b][c] = 0.f;

    load_stage(0, 0);

    const int NKT = DH / BK;   // 8
    for (int k = 0; k < NKT; k++) {
        if (k + 1 < NKT) {
            load_stage((k + 1) & 1, (k + 1) * BK);
            asm volatile("cp.async.wait_group 1;\n");
        } else {
            asm volatile("cp.async.wait_group 0;\n");
        }
        __syncthreads();

        uint32_t sA = (k & 1) ? sA1 : sA0;
        uint32_t sB = (k & 1) ? sB1 : sB0;
#pragma unroll
        for (int ks = 0; ks < 4; ks++) {
            uint32_t a[2][4];
#pragma unroll
            for (int mt = 0; mt < 2; mt++) {
                uint32_t row = wm * 32 + mt * 16 + (lane & 15);
                uint32_t g   = ks * 2 + (lane >> 4);
                uint32_t addr = sA + sw_off(row, g);
                asm volatile(
                    "ldmatrix.sync.aligned.m8n8.x4.shared.b16 {%0,%1,%2,%3}, [%4];"
                    : "=r"(a[mt][0]), "=r"(a[mt][1]), "=r"(a[mt][2]), "=r"(a[mt][3])
                    : "r"(addr));
            }
            uint32_t b[4][2];
#pragma unroll
            for (int half = 0; half < 2; half++) {
                uint32_t row = ks * 16 + (lane & 15);
                uint32_t g   = wn * 4 + half * 2 + (lane >> 4);
                uint32_t addr = sB + sw_off(row, g);
                uint32_t r0, r1, r2, r3;
                asm volatile(
                    "ldmatrix.sync.aligned.m8n8.x4.trans.shared.b16 {%0,%1,%2,%3}, [%4];"
                    : "=r"(r0), "=r"(r1), "=r"(r2), "=r"(r3)
                    : "r"(addr));
                b[half * 2 + 0][0] = r0; b[half * 2 + 0][1] = r1;
                b[half * 2 + 1][0] = r2; b[half * 2 + 1][1] = r3;
            }
#pragma unroll
            for (int mt = 0; mt < 2; mt++)
#pragma unroll
                for (int nt = 0; nt < 4; nt++) {
                    asm volatile(
                        "mma.sync.aligned.m16n8k16.row.col.f32.bf16.bf16.f32 "
                        "{%0,%1,%2,%3}, {%4,%5,%6,%7}, {%8,%9}, {%0,%1,%2,%3};"
                        : "+f"(acc[mt][nt][0]), "+f"(acc[mt][nt][1]),
                          "+f"(acc[mt][nt][2]), "+f"(acc[mt][nt][3])
                        : "r"(a[mt][0]), "r"(a[mt][1]), "r"(a[mt][2]), "r"(a[mt][3]),
                          "r"(b[nt][0]), "r"(b[nt][1]));
                }
        }
        __syncthreads();
    }

    // epilogue: add bias, scatter into out at selected group.
    const int gsel = bn >> 2;  // (bn*64)/256: which of the two selected slots
#pragma unroll
    for (int mt = 0; mt < 2; mt++) {
#pragma unroll
        for (int rr = 0; rr < 2; rr++) {
            int tok = bm * BM + wm * 32 + mt * 16 + (lane >> 2) + rr * 8;
            int grp = g_idx[tok * 2 + gsel];
            float* orow = out + (size_t)tok * DMODEL + grp * HDG;
#pragma unroll
            for (int nt = 0; nt < 4; nt++) {
                int c  = bn * BN + wn * 32 + nt * 8 + (lane & 3) * 2;
                int cl = c & (HDG - 1);
                float2 bv = *(const float2*)(bias + c);
                float2 v;
                v.x = acc[mt][nt][rr * 2 + 0] + bv.x;
                v.y = acc[mt][nt][rr * 2 + 1] + bv.y;
                *(float2*)(orow + cl) = v;
            }
        }
    }
}

// ---------------- launch ----------------
extern "C" void kernel_launch(void* const* d_in, const int* in_sizes, int n_in,
                              void* d_out, int out_size) {
    const float* x    = (const float*)d_in[0];
    const float* Wg   = (const float*)d_in[1];
    const float* Wm   = (const float*)d_in[2];
    const float* bias = (const float*)d_in[3];
    float* out = (float*)d_out;

    convert_wm<<<1024, 256>>>(Wm);
    gate_kernel<<<NTOK / TOKPB, 256>>>(x, Wg, out);
    dim3 grid(DH / BN, NTOK / BM);
    gemm_scatter<<<grid, 256>>>(bias, out);
}